// round 3
// baseline (speedup 1.0000x reference)
#include <cuda_runtime.h>

#define N_TOK 16384
#define HID   768
#define INTER 3072
#define NH    12
#define DH    64
#define MIDW  5376   // 3*HID + INTER
#define COMBW 3840   // HID + INTER

typedef unsigned long long ull;

// -------- scratch (device globals; no allocation allowed) --------
__device__ float g_xn  [N_TOK * HID];     //  50 MB
__device__ float g_mid [N_TOK * MIDW];    // 352 MB
__device__ float g_comb[N_TOK * COMBW];   // 252 MB

// -------- packed f32x2 helpers (Blackwell FFMA2 pipe) --------
__device__ __forceinline__ ull pack2(float lo, float hi) {
    ull r; asm("mov.b64 %0, {%1, %2};" : "=l"(r) : "f"(lo), "f"(hi)); return r;
}
__device__ __forceinline__ void unpack2(ull v, float& lo, float& hi) {
    asm("mov.b64 {%0, %1}, %2;" : "=f"(lo), "=f"(hi) : "l"(v));
}
__device__ __forceinline__ void fma2(ull& c, ull a, ull b) {
    asm("fma.rn.f32x2 %0, %1, %2, %0;" : "+l"(c) : "l"(a), "l"(b));
}

// ============================================================
// LayerNorm: one block per row, 256 threads, 3 elems/thread
// ============================================================
__global__ __launch_bounds__(256) void ln_kernel(
    const float* __restrict__ x, const float* __restrict__ gamma,
    const float* __restrict__ beta, float* __restrict__ xn)
{
    const int row = blockIdx.x;
    const int tid = threadIdx.x;
    const float* xr = x + (size_t)row * HID;
    float v0 = xr[tid], v1 = xr[tid + 256], v2 = xr[tid + 512];
    float s  = v0 + v1 + v2;
    float sq = v0 * v0 + v1 * v1 + v2 * v2;
    #pragma unroll
    for (int o = 16; o > 0; o >>= 1) {
        s  += __shfl_xor_sync(0xffffffffu, s,  o);
        sq += __shfl_xor_sync(0xffffffffu, sq, o);
    }
    __shared__ float ss[8], sqs[8];
    __shared__ float mu_s, rstd_s;
    if ((tid & 31) == 0) { ss[tid >> 5] = s; sqs[tid >> 5] = sq; }
    __syncthreads();
    if (tid == 0) {
        float S = 0.f, SQ = 0.f;
        #pragma unroll
        for (int i = 0; i < 8; i++) { S += ss[i]; SQ += sqs[i]; }
        float mu  = S * (1.0f / HID);
        float var = SQ * (1.0f / HID) - mu * mu;
        mu_s = mu;
        rstd_s = rsqrtf(var + 1e-5f);
    }
    __syncthreads();
    float mu = mu_s, r = rstd_s;
    float* xo = xn + (size_t)row * HID;
    xo[tid]       = (v0 - mu) * r * gamma[tid]       + beta[tid];
    xo[tid + 256] = (v1 - mu) * r * gamma[tid + 256] + beta[tid + 256];
    xo[tid + 512] = (v2 - mu) * r * gamma[tid + 512] + beta[tid + 512];
}

// ============================================================
// SGEMM: C[M,N] = A[M,K] @ B[K,N] + bias (+ resid), fp32,
// 128x128x16 tiles, 256 threads, 8x8 per thread via fma.rn.f32x2
// ============================================================
template<bool RES>
__global__ __launch_bounds__(256) void sgemm_kernel(
    const float* __restrict__ A, const float* __restrict__ B,
    const float* __restrict__ bias, const float* __restrict__ resid,
    float* __restrict__ C, int M, int N, int K)
{
    __shared__ float As[16][128];
    __shared__ float Bs[16][128];
    const int tid = threadIdx.x;
    const int bm = blockIdx.y, bn = blockIdx.x;
    const int arow = tid >> 2,  acol = (tid & 3) << 2;
    const int brow = tid >> 5,  bcol = (tid & 31) << 2;
    const float* Ag = A + (size_t)(bm * 128 + arow) * K + acol;
    const float* Bg = B + (size_t)brow * N + bn * 128 + bcol;
    const int ty = tid >> 4, tx = tid & 15;
    const int m0 = ty * 8, n0 = tx * 8;

    ull acc[4][8];
    #pragma unroll
    for (int i = 0; i < 4; i++)
        #pragma unroll
        for (int j = 0; j < 8; j++) acc[i][j] = 0ull;

    for (int kt = 0; kt < K; kt += 16) {
        float4 a0 = *(const float4*)Ag;
        float4 a1 = *(const float4*)(Ag + (size_t)64 * K);
        float4 b0 = *(const float4*)Bg;
        float4 b1 = *(const float4*)(Bg + (size_t)8 * N);
        __syncthreads();
        As[acol + 0][arow] = a0.x; As[acol + 1][arow] = a0.y;
        As[acol + 2][arow] = a0.z; As[acol + 3][arow] = a0.w;
        As[acol + 0][arow + 64] = a1.x; As[acol + 1][arow + 64] = a1.y;
        As[acol + 2][arow + 64] = a1.z; As[acol + 3][arow + 64] = a1.w;
        *(float4*)&Bs[brow][bcol]     = b0;
        *(float4*)&Bs[brow + 8][bcol] = b1;
        __syncthreads();
        #pragma unroll
        for (int k = 0; k < 16; k++) {
            const ull* A64 = (const ull*)&As[k][m0];
            ull a2_[4] = { A64[0], A64[1], A64[2], A64[3] };
            float4 bb0 = *(const float4*)&Bs[k][n0];
            float4 bb1 = *(const float4*)&Bs[k][n0 + 4];
            ull b2_[8] = { pack2(bb0.x, bb0.x), pack2(bb0.y, bb0.y),
                           pack2(bb0.z, bb0.z), pack2(bb0.w, bb0.w),
                           pack2(bb1.x, bb1.x), pack2(bb1.y, bb1.y),
                           pack2(bb1.z, bb1.z), pack2(bb1.w, bb1.w) };
            #pragma unroll
            for (int i = 0; i < 4; i++)
                #pragma unroll
                for (int j = 0; j < 8; j++)
                    fma2(acc[i][j], a2_[i], b2_[j]);
        }
        Ag += 16;
        Bg += (size_t)16 * N;
    }

    const int colbase = bn * 128 + n0;
    float4 bias0 = *(const float4*)&bias[colbase];
    float4 bias1 = *(const float4*)&bias[colbase + 4];
    float bi[8] = { bias0.x, bias0.y, bias0.z, bias0.w,
                    bias1.x, bias1.y, bias1.z, bias1.w };
    #pragma unroll
    for (int i = 0; i < 4; i++) {
        const int row0 = bm * 128 + m0 + 2 * i;
        float lo[8], hi[8];
        #pragma unroll
        for (int j = 0; j < 8; j++) {
            unpack2(acc[i][j], lo[j], hi[j]);
            lo[j] += bi[j];
            hi[j] += bi[j];
        }
        if (RES) {
            float4 r00 = *(const float4*)&resid[(size_t)row0 * N + colbase];
            float4 r01 = *(const float4*)&resid[(size_t)row0 * N + colbase + 4];
            float4 r10 = *(const float4*)&resid[(size_t)(row0 + 1) * N + colbase];
            float4 r11 = *(const float4*)&resid[(size_t)(row0 + 1) * N + colbase + 4];
            lo[0] += r00.x; lo[1] += r00.y; lo[2] += r00.z; lo[3] += r00.w;
            lo[4] += r01.x; lo[5] += r01.y; lo[6] += r01.z; lo[7] += r01.w;
            hi[0] += r10.x; hi[1] += r10.y; hi[2] += r10.z; hi[3] += r10.w;
            hi[4] += r11.x; hi[5] += r11.y; hi[6] += r11.z; hi[7] += r11.w;
        }
        *(float4*)&C[(size_t)row0 * N + colbase]           = make_float4(lo[0], lo[1], lo[2], lo[3]);
        *(float4*)&C[(size_t)row0 * N + colbase + 4]       = make_float4(lo[4], lo[5], lo[6], lo[7]);
        *(float4*)&C[(size_t)(row0 + 1) * N + colbase]     = make_float4(hi[0], hi[1], hi[2], hi[3]);
        *(float4*)&C[(size_t)(row0 + 1) * N + colbase + 4] = make_float4(hi[4], hi[5], hi[6], hi[7]);
    }
}

// ============================================================
// RoPE in-place on q and k slices of g_mid
// one thread per (token, rotation-pair); handles q and k
// ============================================================
__global__ __launch_bounds__(256) void rope_kernel(
    const float* __restrict__ psin, const float* __restrict__ pcos)
{
    const int idx = blockIdx.x * 256 + threadIdx.x;   // 0 .. N_TOK*384-1
    const int n = idx / 384;
    const int r = idx - n * 384;                      // h*32 + pair
    const int col = r * 2;                            // column within q block
    const int d = col & 63;                           // dim within head (even)
    const float s  = psin[n * 64 + d];
    const float cc = pcos[n * 64 + d];
    float* qp = g_mid + (size_t)n * MIDW + col;
    float* kp = qp + HID;
    float2 qv = *(float2*)qp;
    float2 kv = *(float2*)kp;
    *(float2*)qp = make_float2(qv.x * cc - qv.y * s, qv.y * cc + qv.x * s);
    *(float2*)kp = make_float2(kv.x * cc - kv.y * s, kv.y * cc + kv.x * s);
}

// ============================================================
// Chunked local attention: block = (chunk, head), thread = query row.
// q + output accumulator in registers, K/V streamed via smem (32-key tiles),
// online softmax, dead tiles skipped per-thread.
// ============================================================
__global__ __launch_bounds__(256) void attn_kernel(const int* __restrict__ lenp)
{
    __shared__ float ksm[32 * 64];
    __shared__ float vsm[32 * 64];
    const int c = blockIdx.x, h = blockIdx.y;
    const int ti = threadIdx.x;
    const int qi = c * 256 + ti;
    const unsigned lm = ~((unsigned)(*lenp) - 1u);
    const unsigned qseg = (unsigned)qi & lm;

    float q[64];
    {
        const float* qr = g_mid + (size_t)qi * MIDW + h * DH;
        #pragma unroll
        for (int d4 = 0; d4 < 16; d4++) {
            float4 t = *(const float4*)(qr + 4 * d4);
            q[4 * d4] = t.x; q[4 * d4 + 1] = t.y; q[4 * d4 + 2] = t.z; q[4 * d4 + 3] = t.w;
        }
    }
    float oacc[64];
    #pragma unroll
    for (int d = 0; d < 64; d++) oacc[d] = 0.f;
    float mrun = -1e30f, lrun = 0.f;
    const int base = c * 256 - 256;   // kj = base + j, j in [0,512)

    for (int kt = 0; kt < 16; kt++) {
        const int j0 = kt * 32;
        // cooperative K/V tile load (zeros for kj < 0)
        #pragma unroll
        for (int it = 0; it < 2; it++) {
            int idx = ti + it * 256;
            int rr = idx >> 4, dd = (idx & 15) << 2;
            int n = base + j0 + rr;
            float4 kv = make_float4(0.f, 0.f, 0.f, 0.f);
            float4 vv = kv;
            if (n >= 0) {
                const float* kp = g_mid + (size_t)n * MIDW + HID     + h * DH + dd;
                const float* vp = g_mid + (size_t)n * MIDW + 2 * HID + h * DH + dd;
                kv = *(const float4*)kp;
                vv = *(const float4*)vp;
            }
            *(float4*)&ksm[rr * 64 + dd] = kv;
            *(float4*)&vsm[rr * 64 + dd] = vv;
        }
        __syncthreads();

        // this thread's valid j-window is (ti, ti+256]
        const bool live = (j0 + 31 > ti) && (j0 <= ti + 256);
        if (live) {
            float s[32];
            #pragma unroll
            for (int r = 0; r < 32; r++) {
                float d0 = 0.f, d1 = 0.f, d2 = 0.f, d3 = 0.f;
                #pragma unroll
                for (int d4 = 0; d4 < 16; d4++) {
                    float4 kv = *(const float4*)&ksm[r * 64 + 4 * d4];
                    d0 = fmaf(q[4 * d4],     kv.x, d0);
                    d1 = fmaf(q[4 * d4 + 1], kv.y, d1);
                    d2 = fmaf(q[4 * d4 + 2], kv.z, d2);
                    d3 = fmaf(q[4 * d4 + 3], kv.w, d3);
                }
                s[r] = (d0 + d1) + (d2 + d3);
            }
            float tmax = -1e30f;
            #pragma unroll
            for (int r = 0; r < 32; r++) {
                int j = j0 + r;
                int kj = base + j;
                bool ok = (kj >= 0) && (j > ti) && (j <= ti + 256) &&
                          (((unsigned)kj & lm) == qseg);
                s[r] = ok ? s[r] * 0.125f : -1e30f;
                tmax = fmaxf(tmax, s[r]);
            }
            if (tmax > -1e29f) {
                float mnew = fmaxf(mrun, tmax);
                float corr = __expf(mrun - mnew);
                mrun = mnew;
                lrun *= corr;
                #pragma unroll
                for (int d = 0; d < 64; d++) oacc[d] *= corr;
                #pragma unroll
                for (int r = 0; r < 32; r++) {
                    float p = __expf(s[r] - mnew);
                    lrun += p;
                    #pragma unroll
                    for (int d4 = 0; d4 < 16; d4++) {
                        float4 vv = *(const float4*)&vsm[r * 64 + 4 * d4];
                        oacc[4 * d4]     = fmaf(p, vv.x, oacc[4 * d4]);
                        oacc[4 * d4 + 1] = fmaf(p, vv.y, oacc[4 * d4 + 1]);
                        oacc[4 * d4 + 2] = fmaf(p, vv.z, oacc[4 * d4 + 2]);
                        oacc[4 * d4 + 3] = fmaf(p, vv.w, oacc[4 * d4 + 3]);
                    }
                }
            }
        }
        __syncthreads();
    }

    const float inv = 1.f / lrun;
    float* op = g_comb + (size_t)qi * COMBW + h * DH;
    #pragma unroll
    for (int d4 = 0; d4 < 16; d4++) {
        *(float4*)(op + 4 * d4) = make_float4(oacc[4 * d4] * inv, oacc[4 * d4 + 1] * inv,
                                              oacc[4 * d4 + 2] * inv, oacc[4 * d4 + 3] * inv);
    }
}

// ============================================================
// GELU (tanh approx, matches jax.nn.gelu default) on ff slice
// ============================================================
__device__ __forceinline__ float gelu_tanh(float x) {
    float x3 = x * x * x;
    float u = 0.7978845608028654f * fmaf(0.044715f, x3, x);
    return 0.5f * x * (1.f + tanhf(u));
}

__global__ __launch_bounds__(256) void gelu_kernel()
{
    const int idx = blockIdx.x * 256 + threadIdx.x;   // float4 index, N_TOK*768 total
    const int n = idx / 768;
    const int i4 = idx - n * 768;
    float4 v = *(const float4*)(g_mid + (size_t)n * MIDW + 3 * HID + i4 * 4);
    v.x = gelu_tanh(v.x); v.y = gelu_tanh(v.y);
    v.z = gelu_tanh(v.z); v.w = gelu_tanh(v.w);
    *(float4*)(g_comb + (size_t)n * COMBW + HID + i4 * 4) = v;
}

// ============================================================
extern "C" void kernel_launch(void* const* d_in, const int* in_sizes, int n_in,
                              void* d_out, int out_size)
{
    const float* x     = (const float*)d_in[0];
    // d_in[1] = normed_ages (unused by reference)
    const float* psin  = (const float*)d_in[2];
    const float* pcos  = (const float*)d_in[3];
    const float* gamma = (const float*)d_in[4];
    const float* beta  = (const float*)d_in[5];
    const float* w_in  = (const float*)d_in[6];
    const float* b_in  = (const float*)d_in[7];
    const float* w_out = (const float*)d_in[8];
    const float* b_out = (const float*)d_in[9];
    const int*   lenp  = (const int*)d_in[10];
    float* out = (float*)d_out;

    float *xn, *mid, *comb;
    cudaGetSymbolAddress((void**)&xn,   g_xn);
    cudaGetSymbolAddress((void**)&mid,  g_mid);
    cudaGetSymbolAddress((void**)&comb, g_comb);

    ln_kernel<<<N_TOK, 256>>>(x, gamma, beta, xn);
    sgemm_kernel<false><<<dim3(MIDW / 128, N_TOK / 128), 256>>>(
        xn, w_in, b_in, nullptr, mid, N_TOK, MIDW, HID);
    rope_kernel<<<(N_TOK * 384) / 256, 256>>>(psin, pcos);
    attn_kernel<<<dim3(N_TOK / 256, NH), 256>>>(lenp);
    gelu_kernel<<<(N_TOK * 768) / 256, 256>>>();
    sgemm_kernel<true><<<dim3(HID / 128, N_TOK / 128), 256>>>(
        comb, w_out, b_out, xn, out, N_TOK, HID, COMBW);
}

// round 5
// speedup vs baseline: 2.3675x; 2.3675x over previous
#include <cuda_runtime.h>
#include <cuda_bf16.h>
#include <cstdint>

#define N_TOK 16384
#define HID   768
#define INTER 3072
#define NH    12
#define DH    64
#define MIDW  5376   // 3*HID + INTER
#define COMBW 3840   // HID + INTER
#define QKVW  2304   // 3*HID

typedef unsigned long long ull;

// ================= scratch (device globals) =================
__device__ float         g_xn   [N_TOK * HID];
__device__ __nv_bfloat16 g_xn_h [N_TOK * HID];
__device__ __nv_bfloat16 g_xn_l [N_TOK * HID];
__device__ float         g_qkv  [(size_t)N_TOK * QKVW];
__device__ __nv_bfloat16 g_cmb_h[(size_t)N_TOK * COMBW];
__device__ __nv_bfloat16 g_cmb_l[(size_t)N_TOK * COMBW];
__device__ __nv_bfloat16 g_winT_h[(size_t)MIDW * HID];
__device__ __nv_bfloat16 g_winT_l[(size_t)MIDW * HID];
__device__ __nv_bfloat16 g_woutT_h[(size_t)HID * COMBW];
__device__ __nv_bfloat16 g_woutT_l[(size_t)HID * COMBW];

// ================= helpers =================
__device__ __forceinline__ uint32_t smem_to_u32(const void* p) {
    uint32_t a;
    asm("{ .reg .u64 t; cvta.to.shared.u64 t, %1; cvt.u32.u64 %0, t; }" : "=r"(a) : "l"(p));
    return a;
}
#define SMEM_SWIZZLE_128B(bo) ((bo) ^ (((bo) >> 3) & 0x70))

__device__ __forceinline__ void cp_async16(uint32_t saddr, const void* gaddr) {
    asm volatile("cp.async.cg.shared.global [%0], [%1], 16;" :: "r"(saddr), "l"(gaddr));
}
#define CP_COMMIT() asm volatile("cp.async.commit_group;" ::: "memory")

__device__ __forceinline__ void ldsm4(uint32_t r[4], uint32_t addr) {
    asm volatile("ldmatrix.sync.aligned.m8n8.x4.shared.b16 {%0,%1,%2,%3}, [%4];"
        : "=r"(r[0]), "=r"(r[1]), "=r"(r[2]), "=r"(r[3]) : "r"(addr));
}
__device__ __forceinline__ void mma16816(float c[4], const uint32_t a[4], const uint32_t b[2]) {
    asm volatile(
        "mma.sync.aligned.m16n8k16.row.col.f32.bf16.bf16.f32 "
        "{%0,%1,%2,%3}, {%4,%5,%6,%7}, {%8,%9}, {%0,%1,%2,%3};"
        : "+f"(c[0]), "+f"(c[1]), "+f"(c[2]), "+f"(c[3])
        : "r"(a[0]), "r"(a[1]), "r"(a[2]), "r"(a[3]), "r"(b[0]), "r"(b[1]));
}

__device__ __forceinline__ void split_bf16(float x, __nv_bfloat16& h, __nv_bfloat16& l) {
    h = __float2bfloat16(x);
    l = __float2bfloat16(x - __bfloat162float(h));
}

__device__ __forceinline__ float gelu_tanh(float x) {
    float x3 = x * x * x;
    float u = 0.7978845608028654f * fmaf(0.044715f, x3, x);
    return 0.5f * x * (1.f + tanhf(u));
}

// ============================================================
// LayerNorm: one block per row; writes fp32 xn + bf16 hi/lo
// ============================================================
__global__ __launch_bounds__(256) void ln_kernel(
    const float* __restrict__ x, const float* __restrict__ gamma,
    const float* __restrict__ beta, float* __restrict__ xn,
    __nv_bfloat16* __restrict__ xh, __nv_bfloat16* __restrict__ xl)
{
    const int row = blockIdx.x;
    const int tid = threadIdx.x;
    const float* xr = x + (size_t)row * HID;
    float v0 = xr[tid], v1 = xr[tid + 256], v2 = xr[tid + 512];
    float s  = v0 + v1 + v2;
    float sq = v0 * v0 + v1 * v1 + v2 * v2;
    #pragma unroll
    for (int o = 16; o > 0; o >>= 1) {
        s  += __shfl_xor_sync(0xffffffffu, s,  o);
        sq += __shfl_xor_sync(0xffffffffu, sq, o);
    }
    __shared__ float ss[8], sqs[8];
    __shared__ float mu_s, rstd_s;
    if ((tid & 31) == 0) { ss[tid >> 5] = s; sqs[tid >> 5] = sq; }
    __syncthreads();
    if (tid == 0) {
        float S = 0.f, SQ = 0.f;
        #pragma unroll
        for (int i = 0; i < 8; i++) { S += ss[i]; SQ += sqs[i]; }
        float mu  = S * (1.0f / HID);
        float var = SQ * (1.0f / HID) - mu * mu;
        mu_s = mu;
        rstd_s = rsqrtf(var + 1e-5f);
    }
    __syncthreads();
    float mu = mu_s, r = rstd_s;
    size_t base = (size_t)row * HID;
    #pragma unroll
    for (int it = 0; it < 3; it++) {
        int c = tid + it * 256;
        float v = (it == 0) ? v0 : (it == 1) ? v1 : v2;
        float y = (v - mu) * r * gamma[c] + beta[c];
        xn[base + c] = y;
        __nv_bfloat16 h, l;
        split_bf16(y, h, l);
        xh[base + c] = h;
        xl[base + c] = l;
    }
}

// ============================================================
// Weight transpose + bf16 hi/lo split: W[K,N] -> T[N,K]
// ============================================================
__global__ __launch_bounds__(256) void wtr_kernel(
    const float* __restrict__ W, __nv_bfloat16* __restrict__ Th,
    __nv_bfloat16* __restrict__ Tl, int K, int N)
{
    __shared__ float t[32][33];
    const int nb = blockIdx.x * 32, kb = blockIdx.y * 32;
    const int x = threadIdx.x & 31, y = threadIdx.x >> 5;
    #pragma unroll
    for (int j = 0; j < 32; j += 8)
        t[y + j][x] = W[(size_t)(kb + y + j) * N + nb + x];
    __syncthreads();
    #pragma unroll
    for (int j = 0; j < 32; j += 8) {
        float v = t[x][y + j];
        __nv_bfloat16 h, l;
        split_bf16(v, h, l);
        size_t o = (size_t)(nb + y + j) * K + kb + x;
        Th[o] = h;
        Tl[o] = l;
    }
}

// ============================================================
// HMMA GEMM: C[M,N] = (Ah+Al)[M,K] @ (Bh+Bl)[N,K]^T (3-term bf16 split)
// 128x128 CTA tile, K-chunk 64, cp.async 2-stage, 8 warps (2x4),
// warp tile 64x32, mma.sync m16n8k16 bf16, fp32 accum.
// EPI=1: GEMM1 epilogue (bias + rope(q,k) -> qkv; gelu+split -> comb)
// EPI=0: GEMM2 epilogue (bias + residual -> out)
// ============================================================
#define GEMM_SMEM (2 * 65536)

template<int EPI>
__global__ __launch_bounds__(256, 1) void gemm_kernel(
    const __nv_bfloat16* __restrict__ Ah, const __nv_bfloat16* __restrict__ Al,
    const __nv_bfloat16* __restrict__ Bh, const __nv_bfloat16* __restrict__ Bl,
    int K, const float* __restrict__ bias,
    const float* __restrict__ psin, const float* __restrict__ pcos,
    float* __restrict__ qkv,
    __nv_bfloat16* __restrict__ Ch, __nv_bfloat16* __restrict__ Cl,
    const float* __restrict__ resid, float* __restrict__ outp)
{
    extern __shared__ char smem[];
    const uint32_t sb = smem_to_u32(smem);
    const int tid = threadIdx.x;
    const int wid = tid >> 5, lane = tid & 31;
    const int bn = blockIdx.x, bm = blockIdx.y;
    const int wm = wid >> 2, wn = wid & 3;     // 2 x 4 warp grid
    const int NC = K >> 6;

    float acc[4][4][4];
    #pragma unroll
    for (int i = 0; i < 4; i++)
        #pragma unroll
        for (int j = 0; j < 4; j++)
            #pragma unroll
            for (int e = 0; e < 4; e++) acc[i][j][e] = 0.f;

    const int lm_mat = lane >> 3, lm_r = lane & 7;
    // per-slot load indices
    const int ld_r = tid >> 3, ld_c = tid & 7;   // slot = it*256+tid -> r = ld_r + it*32

    // ---- chunk loader (cp.async, 4 buffers: Ah Al Bh Bl) ----
    #define LOAD_CHUNK(ck) do {                                                   \
        const uint32_t stg = sb + ((ck) & 1) * 65536;                             \
        const int kc = (ck) << 6;                                                 \
        _Pragma("unroll")                                                         \
        for (int it = 0; it < 4; it++) {                                          \
            int r = ld_r + it * 32;                                               \
            uint32_t so = SMEM_SWIZZLE_128B((uint32_t)(r * 128 + ld_c * 16));     \
            size_t rowA = (size_t)(bm * 128 + r) * K + kc + ld_c * 8;             \
            size_t rowB = (size_t)(bn * 128 + r) * K + kc + ld_c * 8;             \
            cp_async16(stg + so,         Ah + rowA);                              \
            cp_async16(stg + 16384 + so, Al + rowA);                              \
            cp_async16(stg + 32768 + so, Bh + rowB);                              \
            cp_async16(stg + 49152 + so, Bl + rowB);                              \
        }                                                                         \
        CP_COMMIT();                                                              \
    } while (0)

    LOAD_CHUNK(0);

    for (int ck = 0; ck < NC; ck++) {
        if (ck + 1 < NC) {
            LOAD_CHUNK(ck + 1);
            asm volatile("cp.async.wait_group 1;" ::: "memory");
        } else {
            asm volatile("cp.async.wait_group 0;" ::: "memory");
        }
        __syncthreads();

        const uint32_t sA = sb + (ck & 1) * 65536;
        const uint32_t sB = sA + 32768;
        #pragma unroll
        for (int ks = 0; ks < 4; ks++) {
            uint32_t ah[4][4], al[4][4], bh[4][2], bl[4][2];
            #pragma unroll
            for (int mi = 0; mi < 4; mi++) {
                int row  = wm * 64 + mi * 16 + lm_r + (lm_mat & 1) * 8;
                int kcol = ks * 16 + (lm_mat >> 1) * 8;
                uint32_t so = SMEM_SWIZZLE_128B((uint32_t)(row * 128 + kcol * 2));
                ldsm4(ah[mi], sA + so);
                ldsm4(al[mi], sA + 16384 + so);
            }
            #pragma unroll
            for (int jp = 0; jp < 2; jp++) {
                int row  = wn * 32 + (jp * 2 + (lm_mat >> 1)) * 8 + lm_r;
                int kcol = ks * 16 + (lm_mat & 1) * 8;
                uint32_t so = SMEM_SWIZZLE_128B((uint32_t)(row * 128 + kcol * 2));
                uint32_t t[4];
                ldsm4(t, sB + so);
                bh[jp * 2][0] = t[0]; bh[jp * 2][1] = t[1];
                bh[jp * 2 + 1][0] = t[2]; bh[jp * 2 + 1][1] = t[3];
                ldsm4(t, sB + 16384 + so);
                bl[jp * 2][0] = t[0]; bl[jp * 2][1] = t[1];
                bl[jp * 2 + 1][0] = t[2]; bl[jp * 2 + 1][1] = t[3];
            }
            #pragma unroll
            for (int mi = 0; mi < 4; mi++)
                #pragma unroll
                for (int nj = 0; nj < 4; nj++) {
                    mma16816(acc[mi][nj], ah[mi], bh[nj]);
                    mma16816(acc[mi][nj], ah[mi], bl[nj]);
                    mma16816(acc[mi][nj], al[mi], bh[nj]);
                }
        }
        __syncthreads();
    }
    #undef LOAD_CHUNK

    // ---------------- epilogue ----------------
    // fragment (mi,nj): rows bm*128 + wm*64 + mi*16 + lane/4 + {0,8},
    //                   cols bn*128 + wn*32 + nj*8 + 2*(lane%4) + {0,1}
    const int r0 = bm * 128 + wm * 64 + (lane >> 2);
    const int c0 = bn * 128 + wn * 32 + (lane & 3) * 2;

    #pragma unroll
    for (int mi = 0; mi < 4; mi++) {
        #pragma unroll
        for (int h = 0; h < 2; h++) {
            const int row = r0 + mi * 16 + h * 8;
            #pragma unroll
            for (int nj = 0; nj < 4; nj++) {
                const int col = c0 + nj * 8;
                float e = acc[mi][nj][h * 2]     + bias[col];
                float o = acc[mi][nj][h * 2 + 1] + bias[col + 1];
                if (EPI == 1) {
                    if (bn < 12) {   // q or k: RoPE (sin/cos repeated per pair)
                        const int d = col & 63;
                        float sn = psin[(size_t)row * 64 + d];
                        float cs = pcos[(size_t)row * 64 + d];
                        float ne = e * cs - o * sn;
                        float no = o * cs + e * sn;
                        e = ne; o = no;
                    }
                    if (bn < 18) {   // q/k/v -> fp32 qkv
                        *(float2*)(qkv + (size_t)row * QKVW + col) = make_float2(e, o);
                    } else {         // ff -> gelu -> bf16 hi/lo comb
                        float g0 = gelu_tanh(e), g1 = gelu_tanh(o);
                        __nv_bfloat16 h0, l0, h1, l1;
                        split_bf16(g0, h0, l0);
                        split_bf16(g1, h1, l1);
                        __nv_bfloat162 hh; hh.x = h0; hh.y = h1;
                        __nv_bfloat162 ll; ll.x = l0; ll.y = l1;
                        size_t cb = (size_t)row * COMBW + (col - 1536);
                        *(__nv_bfloat162*)(Ch + cb) = hh;
                        *(__nv_bfloat162*)(Cl + cb) = ll;
                    }
                } else {
                    const float* rp = resid + (size_t)row * HID + col;
                    *(float2*)(outp + (size_t)row * HID + col) =
                        make_float2(e + rp[0], o + rp[1]);
                }
            }
        }
    }
}

// ============================================================
// Chunked local attention (reads fp32 qkv, writes bf16 hi/lo comb)
// ============================================================
__global__ __launch_bounds__(256) void attn_kernel(
    const int* __restrict__ lenp, const float* __restrict__ qkv,
    __nv_bfloat16* __restrict__ Ch, __nv_bfloat16* __restrict__ Cl)
{
    __shared__ float ksm[32 * 64];
    __shared__ float vsm[32 * 64];
    const int c = blockIdx.x, head = blockIdx.y;
    const int ti = threadIdx.x;
    const int qi = c * 256 + ti;
    const unsigned lm = ~((unsigned)(*lenp) - 1u);
    const unsigned qseg = (unsigned)qi & lm;

    float q[64];
    {
        const float* qr = qkv + (size_t)qi * QKVW + head * DH;
        #pragma unroll
        for (int d4 = 0; d4 < 16; d4++) {
            float4 t = *(const float4*)(qr + 4 * d4);
            q[4 * d4] = t.x; q[4 * d4 + 1] = t.y; q[4 * d4 + 2] = t.z; q[4 * d4 + 3] = t.w;
        }
    }
    float oacc[64];
    #pragma unroll
    for (int d = 0; d < 64; d++) oacc[d] = 0.f;
    float mrun = -1e30f, lrun = 0.f;
    const int base = c * 256 - 256;

    for (int kt = 0; kt < 16; kt++) {
        const int j0 = kt * 32;
        #pragma unroll
        for (int it = 0; it < 2; it++) {
            int idx = ti + it * 256;
            int rr = idx >> 4, dd = (idx & 15) << 2;
            int n = base + j0 + rr;
            float4 kv = make_float4(0.f, 0.f, 0.f, 0.f);
            float4 vv = kv;
            if (n >= 0) {
                const float* kp = qkv + (size_t)n * QKVW + HID     + head * DH + dd;
                const float* vp = qkv + (size_t)n * QKVW + 2 * HID + head * DH + dd;
                kv = *(const float4*)kp;
                vv = *(const float4*)vp;
            }
            *(float4*)&ksm[rr * 64 + dd] = kv;
            *(float4*)&vsm[rr * 64 + dd] = vv;
        }
        __syncthreads();

        const bool live = (j0 + 31 > ti) && (j0 <= ti + 256);
        if (live) {
            float s[32];
            #pragma unroll
            for (int r = 0; r < 32; r++) {
                float d0 = 0.f, d1 = 0.f, d2 = 0.f, d3 = 0.f;
                #pragma unroll
                for (int d4 = 0; d4 < 16; d4++) {
                    float4 kv = *(const float4*)&ksm[r * 64 + 4 * d4];
                    d0 = fmaf(q[4 * d4],     kv.x, d0);
                    d1 = fmaf(q[4 * d4 + 1], kv.y, d1);
                    d2 = fmaf(q[4 * d4 + 2], kv.z, d2);
                    d3 = fmaf(q[4 * d4 + 3], kv.w, d3);
                }
                s[r] = (d0 + d1) + (d2 + d3);
            }
            float tmax = -1e30f;
            #pragma unroll
            for (int r = 0; r < 32; r++) {
                int j = j0 + r;
                int kj = base + j;
                bool ok = (kj >= 0) && (j > ti) && (j <= ti + 256) &&
                          (((unsigned)kj & lm) == qseg);
                s[r] = ok ? s[r] * 0.125f : -1e30f;
                tmax = fmaxf(tmax, s[r]);
            }
            if (tmax > -1e29f) {
                float mnew = fmaxf(mrun, tmax);
                float corr = __expf(mrun - mnew);
                mrun = mnew;
                lrun *= corr;
                #pragma unroll
                for (int d = 0; d < 64; d++) oacc[d] *= corr;
                #pragma unroll
                for (int r = 0; r < 32; r++) {
                    float p = __expf(s[r] - mnew);
                    lrun += p;
                    #pragma unroll
                    for (int d4 = 0; d4 < 16; d4++) {
                        float4 vv = *(const float4*)&vsm[r * 64 + 4 * d4];
                        oacc[4 * d4]     = fmaf(p, vv.x, oacc[4 * d4]);
                        oacc[4 * d4 + 1] = fmaf(p, vv.y, oacc[4 * d4 + 1]);
                        oacc[4 * d4 + 2] = fmaf(p, vv.z, oacc[4 * d4 + 2]);
                        oacc[4 * d4 + 3] = fmaf(p, vv.w, oacc[4 * d4 + 3]);
                    }
                }
            }
        }
        __syncthreads();
    }

    const float inv = 1.f / lrun;
    const size_t ob = (size_t)qi * COMBW + head * DH;
    #pragma unroll
    for (int d = 0; d < 64; d += 2) {
        float o0 = oacc[d] * inv, o1 = oacc[d + 1] * inv;
        __nv_bfloat16 h0, l0, h1, l1;
        split_bf16(o0, h0, l0);
        split_bf16(o1, h1, l1);
        __nv_bfloat162 hh; hh.x = h0; hh.y = h1;
        __nv_bfloat162 ll; ll.x = l0; ll.y = l1;
        *(__nv_bfloat162*)(Ch + ob + d) = hh;
        *(__nv_bfloat162*)(Cl + ob + d) = ll;
    }
}

// ============================================================
extern "C" void kernel_launch(void* const* d_in, const int* in_sizes, int n_in,
                              void* d_out, int out_size)
{
    const float* x     = (const float*)d_in[0];
    const float* psin  = (const float*)d_in[2];
    const float* pcos  = (const float*)d_in[3];
    const float* gamma = (const float*)d_in[4];
    const float* beta  = (const float*)d_in[5];
    const float* w_in  = (const float*)d_in[6];
    const float* b_in  = (const float*)d_in[7];
    const float* w_out = (const float*)d_in[8];
    const float* b_out = (const float*)d_in[9];
    const int*   lenp  = (const int*)d_in[10];
    float* out = (float*)d_out;

    float *xn, *qkv;
    __nv_bfloat16 *xh, *xl, *ch, *cl, *wih, *wil, *woh, *wol;
    cudaGetSymbolAddress((void**)&xn,  g_xn);
    cudaGetSymbolAddress((void**)&xh,  g_xn_h);
    cudaGetSymbolAddress((void**)&xl,  g_xn_l);
    cudaGetSymbolAddress((void**)&qkv, g_qkv);
    cudaGetSymbolAddress((void**)&ch,  g_cmb_h);
    cudaGetSymbolAddress((void**)&cl,  g_cmb_l);
    cudaGetSymbolAddress((void**)&wih, g_winT_h);
    cudaGetSymbolAddress((void**)&wil, g_winT_l);
    cudaGetSymbolAddress((void**)&woh, g_woutT_h);
    cudaGetSymbolAddress((void**)&wol, g_woutT_l);

    cudaFuncSetAttribute(gemm_kernel<1>, cudaFuncAttributeMaxDynamicSharedMemorySize, GEMM_SMEM);
    cudaFuncSetAttribute(gemm_kernel<0>, cudaFuncAttributeMaxDynamicSharedMemorySize, GEMM_SMEM);

    ln_kernel<<<N_TOK, 256>>>(x, gamma, beta, xn, xh, xl);
    wtr_kernel<<<dim3(MIDW / 32, HID / 32), 256>>>(w_in, wih, wil, HID, MIDW);
    wtr_kernel<<<dim3(HID / 32, COMBW / 32), 256>>>(w_out, woh, wol, COMBW, HID);

    gemm_kernel<1><<<dim3(MIDW / 128, N_TOK / 128), 256, GEMM_SMEM>>>(
        xh, xl, wih, wil, HID, b_in, psin, pcos, qkv, ch, cl, nullptr, nullptr);

    attn_kernel<<<dim3(N_TOK / 256, NH), 256>>>(lenp, qkv, ch, cl);

    gemm_kernel<0><<<dim3(HID / 128, N_TOK / 128), 256, GEMM_SMEM>>>(
        ch, cl, woh, wol, COMBW, b_out, nullptr, nullptr, nullptr, nullptr, nullptr, xn, out);
}

// round 6
// speedup vs baseline: 3.1110x; 1.3140x over previous
#include <cuda_runtime.h>
#include <cuda_bf16.h>
#include <cstdint>

#define N_TOK 16384
#define HID   768
#define INTER 3072
#define NH    12
#define DH    64
#define MIDW  5376   // 3*HID + INTER
#define COMBW 3840   // HID + INTER
#define QKVW  2304   // 3*HID

typedef unsigned long long ull;

// ================= scratch (device globals) =================
__device__ float         g_xn   [N_TOK * HID];
__device__ __nv_bfloat16 g_xn_h [N_TOK * HID];
__device__ __nv_bfloat16 g_xn_l [N_TOK * HID];
__device__ __nv_bfloat16 g_qkv_h[(size_t)N_TOK * QKVW];
__device__ __nv_bfloat16 g_qkv_l[(size_t)N_TOK * QKVW];
__device__ __nv_bfloat16 g_cmb_h[(size_t)N_TOK * COMBW];
__device__ __nv_bfloat16 g_cmb_l[(size_t)N_TOK * COMBW];
__device__ __nv_bfloat16 g_winT_h[(size_t)MIDW * HID];
__device__ __nv_bfloat16 g_winT_l[(size_t)MIDW * HID];
__device__ __nv_bfloat16 g_woutT_h[(size_t)HID * COMBW];
__device__ __nv_bfloat16 g_woutT_l[(size_t)HID * COMBW];

// ================= helpers =================
__device__ __forceinline__ uint32_t smem_to_u32(const void* p) {
    uint32_t a;
    asm("{ .reg .u64 t; cvta.to.shared.u64 t, %1; cvt.u32.u64 %0, t; }" : "=r"(a) : "l"(p));
    return a;
}
#define SMEM_SWIZZLE_128B(bo) ((bo) ^ (((bo) >> 3) & 0x70))

__device__ __forceinline__ void cp_async16(uint32_t saddr, const void* gaddr) {
    asm volatile("cp.async.cg.shared.global [%0], [%1], 16;" :: "r"(saddr), "l"(gaddr));
}
__device__ __forceinline__ void cp_async16z(uint32_t saddr, const void* gaddr, int srcsz) {
    asm volatile("cp.async.cg.shared.global [%0], [%1], 16, %2;"
                 :: "r"(saddr), "l"(gaddr), "r"(srcsz));
}
#define CP_COMMIT() asm volatile("cp.async.commit_group;" ::: "memory")

__device__ __forceinline__ void ldsm4(uint32_t r[4], uint32_t addr) {
    asm volatile("ldmatrix.sync.aligned.m8n8.x4.shared.b16 {%0,%1,%2,%3}, [%4];"
        : "=r"(r[0]), "=r"(r[1]), "=r"(r[2]), "=r"(r[3]) : "r"(addr));
}
__device__ __forceinline__ void ldsm4t(uint32_t r[4], uint32_t addr) {
    asm volatile("ldmatrix.sync.aligned.m8n8.x4.trans.shared.b16 {%0,%1,%2,%3}, [%4];"
        : "=r"(r[0]), "=r"(r[1]), "=r"(r[2]), "=r"(r[3]) : "r"(addr));
}
__device__ __forceinline__ void mma16816(float c[4], const uint32_t a[4], const uint32_t b[2]) {
    asm volatile(
        "mma.sync.aligned.m16n8k16.row.col.f32.bf16.bf16.f32 "
        "{%0,%1,%2,%3}, {%4,%5,%6,%7}, {%8,%9}, {%0,%1,%2,%3};"
        : "+f"(c[0]), "+f"(c[1]), "+f"(c[2]), "+f"(c[3])
        : "r"(a[0]), "r"(a[1]), "r"(a[2]), "r"(a[3]), "r"(b[0]), "r"(b[1]));
}

__device__ __forceinline__ void split_bf16(float x, __nv_bfloat16& h, __nv_bfloat16& l) {
    h = __float2bfloat16(x);
    l = __float2bfloat16(x - __bfloat162float(h));
}
__device__ __forceinline__ uint32_t pack_b(__nv_bfloat16 a, __nv_bfloat16 b) {
    __nv_bfloat162 t; t.x = a; t.y = b;
    return *(uint32_t*)&t;
}

__device__ __forceinline__ float gelu_tanh(float x) {
    float x3 = x * x * x;
    float u = 0.7978845608028654f * fmaf(0.044715f, x3, x);
    return 0.5f * x * (1.f + tanhf(u));
}

// ============================================================
// LayerNorm: one block per row; writes fp32 xn + bf16 hi/lo
// ============================================================
__global__ __launch_bounds__(256) void ln_kernel(
    const float* __restrict__ x, const float* __restrict__ gamma,
    const float* __restrict__ beta, float* __restrict__ xn,
    __nv_bfloat16* __restrict__ xh, __nv_bfloat16* __restrict__ xl)
{
    const int row = blockIdx.x;
    const int tid = threadIdx.x;
    const float* xr = x + (size_t)row * HID;
    float v0 = xr[tid], v1 = xr[tid + 256], v2 = xr[tid + 512];
    float s  = v0 + v1 + v2;
    float sq = v0 * v0 + v1 * v1 + v2 * v2;
    #pragma unroll
    for (int o = 16; o > 0; o >>= 1) {
        s  += __shfl_xor_sync(0xffffffffu, s,  o);
        sq += __shfl_xor_sync(0xffffffffu, sq, o);
    }
    __shared__ float ss[8], sqs[8];
    __shared__ float mu_s, rstd_s;
    if ((tid & 31) == 0) { ss[tid >> 5] = s; sqs[tid >> 5] = sq; }
    __syncthreads();
    if (tid == 0) {
        float S = 0.f, SQ = 0.f;
        #pragma unroll
        for (int i = 0; i < 8; i++) { S += ss[i]; SQ += sqs[i]; }
        float mu  = S * (1.0f / HID);
        float var = SQ * (1.0f / HID) - mu * mu;
        mu_s = mu;
        rstd_s = rsqrtf(var + 1e-5f);
    }
    __syncthreads();
    float mu = mu_s, r = rstd_s;
    size_t base = (size_t)row * HID;
    #pragma unroll
    for (int it = 0; it < 3; it++) {
        int c = tid + it * 256;
        float v = (it == 0) ? v0 : (it == 1) ? v1 : v2;
        float y = (v - mu) * r * gamma[c] + beta[c];
        xn[base + c] = y;
        __nv_bfloat16 h, l;
        split_bf16(y, h, l);
        xh[base + c] = h;
        xl[base + c] = l;
    }
}

// ============================================================
// Weight transpose + bf16 hi/lo split: W[K,N] -> T[N,K]
// ============================================================
__global__ __launch_bounds__(256) void wtr_kernel(
    const float* __restrict__ W, __nv_bfloat16* __restrict__ Th,
    __nv_bfloat16* __restrict__ Tl, int K, int N)
{
    __shared__ float t[32][33];
    const int nb = blockIdx.x * 32, kb = blockIdx.y * 32;
    const int x = threadIdx.x & 31, y = threadIdx.x >> 5;
    #pragma unroll
    for (int j = 0; j < 32; j += 8)
        t[y + j][x] = W[(size_t)(kb + y + j) * N + nb + x];
    __syncthreads();
    #pragma unroll
    for (int j = 0; j < 32; j += 8) {
        float v = t[x][y + j];
        __nv_bfloat16 h, l;
        split_bf16(v, h, l);
        size_t o = (size_t)(nb + y + j) * K + kb + x;
        Th[o] = h;
        Tl[o] = l;
    }
}

// ============================================================
// HMMA GEMM (unchanged mainloop from R5)
// EPI=1: bias + rope(q,k) + 0.125 fold (q) -> qkv bf16 h/l; gelu -> comb h/l
// EPI=0: bias + residual -> out
// ============================================================
#define GEMM_SMEM (2 * 65536)

template<int EPI>
__global__ __launch_bounds__(256, 1) void gemm_kernel(
    const __nv_bfloat16* __restrict__ Ah, const __nv_bfloat16* __restrict__ Al,
    const __nv_bfloat16* __restrict__ Bh, const __nv_bfloat16* __restrict__ Bl,
    int K, const float* __restrict__ bias,
    const float* __restrict__ psin, const float* __restrict__ pcos,
    __nv_bfloat16* __restrict__ qkvh, __nv_bfloat16* __restrict__ qkvl,
    __nv_bfloat16* __restrict__ Ch, __nv_bfloat16* __restrict__ Cl,
    const float* __restrict__ resid, float* __restrict__ outp)
{
    extern __shared__ char smem[];
    const uint32_t sb = smem_to_u32(smem);
    const int tid = threadIdx.x;
    const int wid = tid >> 5, lane = tid & 31;
    const int bn = blockIdx.x, bm = blockIdx.y;
    const int wm = wid >> 2, wn = wid & 3;     // 2 x 4 warp grid
    const int NC = K >> 6;

    float acc[4][4][4];
    #pragma unroll
    for (int i = 0; i < 4; i++)
        #pragma unroll
        for (int j = 0; j < 4; j++)
            #pragma unroll
            for (int e = 0; e < 4; e++) acc[i][j][e] = 0.f;

    const int lm_mat = lane >> 3, lm_r = lane & 7;
    const int ld_r = tid >> 3, ld_c = tid & 7;

    #define LOAD_CHUNK(ck) do {                                                   \
        const uint32_t stg = sb + ((ck) & 1) * 65536;                             \
        const int kc = (ck) << 6;                                                 \
        _Pragma("unroll")                                                         \
        for (int it = 0; it < 4; it++) {                                          \
            int r = ld_r + it * 32;                                               \
            uint32_t so = SMEM_SWIZZLE_128B((uint32_t)(r * 128 + ld_c * 16));     \
            size_t rowA = (size_t)(bm * 128 + r) * K + kc + ld_c * 8;             \
            size_t rowB = (size_t)(bn * 128 + r) * K + kc + ld_c * 8;             \
            cp_async16(stg + so,         Ah + rowA);                              \
            cp_async16(stg + 16384 + so, Al + rowA);                              \
            cp_async16(stg + 32768 + so, Bh + rowB);                              \
            cp_async16(stg + 49152 + so, Bl + rowB);                              \
        }                                                                         \
        CP_COMMIT();                                                              \
    } while (0)

    LOAD_CHUNK(0);

    for (int ck = 0; ck < NC; ck++) {
        if (ck + 1 < NC) {
            LOAD_CHUNK(ck + 1);
            asm volatile("cp.async.wait_group 1;" ::: "memory");
        } else {
            asm volatile("cp.async.wait_group 0;" ::: "memory");
        }
        __syncthreads();

        const uint32_t sA = sb + (ck & 1) * 65536;
        const uint32_t sB = sA + 32768;
        #pragma unroll
        for (int ks = 0; ks < 4; ks++) {
            uint32_t ah[4][4], al[4][4], bh[4][2], bl[4][2];
            #pragma unroll
            for (int mi = 0; mi < 4; mi++) {
                int row  = wm * 64 + mi * 16 + lm_r + (lm_mat & 1) * 8;
                int kcol = ks * 16 + (lm_mat >> 1) * 8;
                uint32_t so = SMEM_SWIZZLE_128B((uint32_t)(row * 128 + kcol * 2));
                ldsm4(ah[mi], sA + so);
                ldsm4(al[mi], sA + 16384 + so);
            }
            #pragma unroll
            for (int jp = 0; jp < 2; jp++) {
                int row  = wn * 32 + (jp * 2 + (lm_mat >> 1)) * 8 + lm_r;
                int kcol = ks * 16 + (lm_mat & 1) * 8;
                uint32_t so = SMEM_SWIZZLE_128B((uint32_t)(row * 128 + kcol * 2));
                uint32_t t[4];
                ldsm4(t, sB + so);
                bh[jp * 2][0] = t[0]; bh[jp * 2][1] = t[1];
                bh[jp * 2 + 1][0] = t[2]; bh[jp * 2 + 1][1] = t[3];
                ldsm4(t, sB + 16384 + so);
                bl[jp * 2][0] = t[0]; bl[jp * 2][1] = t[1];
                bl[jp * 2 + 1][0] = t[2]; bl[jp * 2 + 1][1] = t[3];
            }
            #pragma unroll
            for (int mi = 0; mi < 4; mi++)
                #pragma unroll
                for (int nj = 0; nj < 4; nj++) {
                    mma16816(acc[mi][nj], ah[mi], bh[nj]);
                    mma16816(acc[mi][nj], ah[mi], bl[nj]);
                    mma16816(acc[mi][nj], al[mi], bh[nj]);
                }
        }
        __syncthreads();
    }
    #undef LOAD_CHUNK

    // ---------------- epilogue ----------------
    const int r0 = bm * 128 + wm * 64 + (lane >> 2);
    const int c0 = bn * 128 + wn * 32 + (lane & 3) * 2;

    #pragma unroll
    for (int mi = 0; mi < 4; mi++) {
        #pragma unroll
        for (int h = 0; h < 2; h++) {
            const int row = r0 + mi * 16 + h * 8;
            #pragma unroll
            for (int nj = 0; nj < 4; nj++) {
                const int col = c0 + nj * 8;
                float e = acc[mi][nj][h * 2]     + bias[col];
                float o = acc[mi][nj][h * 2 + 1] + bias[col + 1];
                if (EPI == 1) {
                    if (bn < 12) {   // q or k: RoPE
                        const int d = col & 63;
                        float sn = psin[(size_t)row * 64 + d];
                        float cs = pcos[(size_t)row * 64 + d];
                        float ne = e * cs - o * sn;
                        float no = o * cs + e * sn;
                        e = ne; o = no;
                        if (bn < 6) { e *= 0.125f; o *= 0.125f; }  // fold score scale into q (exact)
                    }
                    if (bn < 18) {   // q/k/v -> bf16 h/l qkv
                        __nv_bfloat16 h0, l0, h1, l1;
                        split_bf16(e, h0, l0);
                        split_bf16(o, h1, l1);
                        size_t qb = (size_t)row * QKVW + col;
                        *(uint32_t*)(qkvh + qb) = pack_b(h0, h1);
                        *(uint32_t*)(qkvl + qb) = pack_b(l0, l1);
                    } else {         // ff -> gelu -> bf16 h/l comb
                        float g0 = gelu_tanh(e), g1 = gelu_tanh(o);
                        __nv_bfloat16 h0, l0, h1, l1;
                        split_bf16(g0, h0, l0);
                        split_bf16(g1, h1, l1);
                        size_t cb = (size_t)row * COMBW + (col - 1536);
                        *(uint32_t*)(Ch + cb) = pack_b(h0, h1);
                        *(uint32_t*)(Cl + cb) = pack_b(l0, l1);
                    }
                } else {
                    const float* rp = resid + (size_t)row * HID + col;
                    *(float2*)(outp + (size_t)row * HID + col) =
                        make_float2(e + rp[0], o + rp[1]);
                }
            }
        }
    }
}

// ============================================================
// HMMA flash attention: block = (chunk of 256 q, head), 8 warps.
// Q staged in smem (64KB, bf16 h/l); 16 key tiles of 32, cp.async
// double-buffered. 3-term bf16 split for QK^T and PV.
// smem: [0,32K) Qh, [32K,64K) Ql, [64K, 64K+2*16K) KV stages
//       stage: Kh(4K) Kl(4K) Vh(4K) Vl(4K)
// ============================================================
#define ATTN_SMEM (65536 + 2 * 16384)

__global__ __launch_bounds__(256, 1) void attn_kernel(
    const int* __restrict__ lenp,
    const __nv_bfloat16* __restrict__ qvh, const __nv_bfloat16* __restrict__ qvl,
    __nv_bfloat16* __restrict__ Ch, __nv_bfloat16* __restrict__ Cl)
{
    extern __shared__ char smem[];
    const uint32_t sb = smem_to_u32(smem);
    const int c = blockIdx.x, head = blockIdx.y;
    const int tid = threadIdx.x, w = tid >> 5, lane = tid & 31;
    const int lm_mat = lane >> 3, lm_r = lane & 7;
    const unsigned lm = ~((unsigned)(*lenp) - 1u);
    const int base = c * 256 - 256;

    // ---- stage Q (h/l) ----
    {
        const int row = tid;
        const size_t qb = (size_t)(c * 256 + row) * QKVW + head * 64;
        #pragma unroll
        for (int i = 0; i < 8; i++) {
            uint32_t so = SMEM_SWIZZLE_128B((uint32_t)(row * 128 + i * 16));
            *(uint4*)(smem + so)         = *(const uint4*)(qvh + qb + i * 8);
            *(uint4*)(smem + 32768 + so) = *(const uint4*)(qvl + qb + i * 8);
        }
    }

    const int krow = tid >> 3, kch = tid & 7;
    const uint32_t kso = SMEM_SWIZZLE_128B((uint32_t)(krow * 128 + kch * 16));

    #define PREFETCH(kt) do {                                                       \
        int key = base + (kt) * 32 + krow;                                          \
        int sz = (key >= 0) ? 16 : 0;                                               \
        int cky = (key < 0) ? 0 : key;                                              \
        size_t kb_ = (size_t)cky * QKVW + HID + head * 64 + kch * 8;                \
        size_t vb_ = kb_ + HID;                                                     \
        uint32_t d = sb + 65536 + ((kt) & 1) * 16384 + kso;                         \
        cp_async16z(d,         qvh + kb_, sz);                                      \
        cp_async16z(d + 4096,  qvl + kb_, sz);                                      \
        cp_async16z(d + 8192,  qvh + vb_, sz);                                      \
        cp_async16z(d + 12288, qvl + vb_, sz);                                      \
        CP_COMMIT();                                                                \
    } while (0)

    float o[2][8][4];
    #pragma unroll
    for (int mi = 0; mi < 2; mi++)
        #pragma unroll
        for (int dj = 0; dj < 8; dj++)
            #pragma unroll
            for (int e = 0; e < 4; e++) o[mi][dj][e] = 0.f;
    float m[2][2] = {{-1e30f, -1e30f}, {-1e30f, -1e30f}};
    float lp[2][2] = {{0.f, 0.f}, {0.f, 0.f}};

    const int qrow0 = c * 256 + w * 32 + (lane >> 2);

    PREFETCH(0);

    for (int kt = 0; kt < 16; kt++) {
        if (kt + 1 < 16) {
            PREFETCH(kt + 1);
            asm volatile("cp.async.wait_group 1;" ::: "memory");
        } else {
            asm volatile("cp.async.wait_group 0;" ::: "memory");
        }
        __syncthreads();

        if (kt >= w && kt <= w + 8) {   // warp-level live window
            const uint32_t stg = sb + 65536 + (kt & 1) * 16384;

            // ---- S = Q @ K^T (3-term) ----
            float s[2][4][4];
            #pragma unroll
            for (int mi = 0; mi < 2; mi++)
                #pragma unroll
                for (int nj = 0; nj < 4; nj++)
                    #pragma unroll
                    for (int e = 0; e < 4; e++) s[mi][nj][e] = 0.f;

            #pragma unroll
            for (int ks = 0; ks < 4; ks++) {
                uint32_t qh[2][4], ql[2][4], kh[4][2], kl[4][2];
                #pragma unroll
                for (int mi = 0; mi < 2; mi++) {
                    int arow = w * 32 + mi * 16 + lm_r + (lm_mat & 1) * 8;
                    uint32_t so = SMEM_SWIZZLE_128B(
                        (uint32_t)(arow * 128 + (ks * 16 + (lm_mat >> 1) * 8) * 2));
                    ldsm4(qh[mi], sb + so);
                    ldsm4(ql[mi], sb + 32768 + so);
                }
                #pragma unroll
                for (int jp = 0; jp < 2; jp++) {
                    int krw = (jp * 2 + (lm_mat >> 1)) * 8 + lm_r;
                    uint32_t so = SMEM_SWIZZLE_128B(
                        (uint32_t)(krw * 128 + (ks * 16 + (lm_mat & 1) * 8) * 2));
                    uint32_t t[4];
                    ldsm4(t, stg + so);
                    kh[jp * 2][0] = t[0]; kh[jp * 2][1] = t[1];
                    kh[jp * 2 + 1][0] = t[2]; kh[jp * 2 + 1][1] = t[3];
                    ldsm4(t, stg + 4096 + so);
                    kl[jp * 2][0] = t[0]; kl[jp * 2][1] = t[1];
                    kl[jp * 2 + 1][0] = t[2]; kl[jp * 2 + 1][1] = t[3];
                }
                #pragma unroll
                for (int mi = 0; mi < 2; mi++)
                    #pragma unroll
                    for (int nj = 0; nj < 4; nj++) {
                        mma16816(s[mi][nj], qh[mi], kh[nj]);
                        mma16816(s[mi][nj], qh[mi], kl[nj]);
                        mma16816(s[mi][nj], ql[mi], kh[nj]);
                    }
            }

            // ---- mask + online softmax ----
            const int kB = base + kt * 32 + (lane & 3) * 2;
            float tm[2][2] = {{-1e30f, -1e30f}, {-1e30f, -1e30f}};
            #pragma unroll
            for (int mi = 0; mi < 2; mi++)
                #pragma unroll
                for (int nj = 0; nj < 4; nj++)
                    #pragma unroll
                    for (int e = 0; e < 4; e++) {
                        int hf = e >> 1;
                        int qi = qrow0 + mi * 16 + hf * 8;
                        int kabs = kB + nj * 8 + (e & 1);
                        int dd = qi - kabs;
                        bool ok = (kabs >= 0) && (dd >= 0) && (dd < 256) &&
                                  (((unsigned)qi & lm) == ((unsigned)kabs & lm));
                        float sv = ok ? s[mi][nj][e] : -1e30f;
                        s[mi][nj][e] = sv;
                        tm[mi][hf] = fmaxf(tm[mi][hf], sv);
                    }
            float corr[2][2];
            #pragma unroll
            for (int mi = 0; mi < 2; mi++)
                #pragma unroll
                for (int hf = 0; hf < 2; hf++) {
                    float t = tm[mi][hf];
                    t = fmaxf(t, __shfl_xor_sync(0xffffffffu, t, 1));
                    t = fmaxf(t, __shfl_xor_sync(0xffffffffu, t, 2));
                    float mn = fmaxf(fmaxf(m[mi][hf], t), -1e20f);
                    corr[mi][hf] = __expf(m[mi][hf] - mn);
                    m[mi][hf] = mn;
                    lp[mi][hf] *= corr[mi][hf];
                }
            #pragma unroll
            for (int mi = 0; mi < 2; mi++)
                #pragma unroll
                for (int dj = 0; dj < 8; dj++)
                    #pragma unroll
                    for (int e = 0; e < 4; e++) o[mi][dj][e] *= corr[mi][e >> 1];
            #pragma unroll
            for (int mi = 0; mi < 2; mi++)
                #pragma unroll
                for (int nj = 0; nj < 4; nj++)
                    #pragma unroll
                    for (int e = 0; e < 4; e++) {
                        float p = __expf(s[mi][nj][e] - m[mi][e >> 1]);
                        s[mi][nj][e] = p;
                        lp[mi][e >> 1] += p;
                    }

            // ---- O += P @ V (3-term, V via ldmatrix.trans) ----
            const uint32_t vB = stg + 8192;
            #pragma unroll
            for (int kv = 0; kv < 2; kv++) {
                uint32_t ah[2][4], al[2][4];
                #pragma unroll
                for (int mi = 0; mi < 2; mi++) {
                    const float* p0 = s[mi][2 * kv];
                    const float* p1 = s[mi][2 * kv + 1];
                    __nv_bfloat16 h[8], l[8];
                    #pragma unroll
                    for (int e = 0; e < 4; e++) {
                        split_bf16(p0[e], h[e], l[e]);
                        split_bf16(p1[e], h[4 + e], l[4 + e]);
                    }
                    ah[mi][0] = pack_b(h[0], h[1]); ah[mi][1] = pack_b(h[2], h[3]);
                    ah[mi][2] = pack_b(h[4], h[5]); ah[mi][3] = pack_b(h[6], h[7]);
                    al[mi][0] = pack_b(l[0], l[1]); al[mi][1] = pack_b(l[2], l[3]);
                    al[mi][2] = pack_b(l[4], l[5]); al[mi][3] = pack_b(l[6], l[7]);
                }
                #pragma unroll
                for (int djp = 0; djp < 4; djp++) {
                    int vrow = kv * 16 + (lm_mat & 1) * 8 + lm_r;
                    int vcb  = djp * 32 + (lm_mat >> 1) * 16;
                    uint32_t so = SMEM_SWIZZLE_128B((uint32_t)(vrow * 128 + vcb));
                    uint32_t th[4], tl[4];
                    ldsm4t(th, vB + so);
                    ldsm4t(tl, vB + 4096 + so);
                    #pragma unroll
                    for (int jj = 0; jj < 2; jj++) {
                        uint32_t bh[2] = { th[jj * 2], th[jj * 2 + 1] };
                        uint32_t bl[2] = { tl[jj * 2], tl[jj * 2 + 1] };
                        int dj = djp * 2 + jj;
                        #pragma unroll
                        for (int mi = 0; mi < 2; mi++) {
                            mma16816(o[mi][dj], ah[mi], bh);
                            mma16816(o[mi][dj], ah[mi], bl);
                            mma16816(o[mi][dj], al[mi], bh);
                        }
                    }
                }
            }
        }
        __syncthreads();
    }
    #undef PREFETCH

    // ---- normalize + write out ----
    float inv[2][2];
    #pragma unroll
    for (int mi = 0; mi < 2; mi++)
        #pragma unroll
        for (int hf = 0; hf < 2; hf++) {
            float l = lp[mi][hf];
            l += __shfl_xor_sync(0xffffffffu, l, 1);
            l += __shfl_xor_sync(0xffffffffu, l, 2);
            inv[mi][hf] = 1.f / l;
        }
    #pragma unroll
    for (int mi = 0; mi < 2; mi++)
        #pragma unroll
        for (int hf = 0; hf < 2; hf++) {
            const int qi = qrow0 + mi * 16 + hf * 8;
            const size_t ob = (size_t)qi * COMBW + head * 64 + (lane & 3) * 2;
            #pragma unroll
            for (int dj = 0; dj < 8; dj++) {
                float e0 = o[mi][dj][hf * 2]     * inv[mi][hf];
                float e1 = o[mi][dj][hf * 2 + 1] * inv[mi][hf];
                __nv_bfloat16 h0, l0, h1, l1;
                split_bf16(e0, h0, l0);
                split_bf16(e1, h1, l1);
                *(uint32_t*)(Ch + ob + dj * 8) = pack_b(h0, h1);
                *(uint32_t*)(Cl + ob + dj * 8) = pack_b(l0, l1);
            }
        }
}

// ============================================================
extern "C" void kernel_launch(void* const* d_in, const int* in_sizes, int n_in,
                              void* d_out, int out_size)
{
    const float* x     = (const float*)d_in[0];
    const float* psin  = (const float*)d_in[2];
    const float* pcos  = (const float*)d_in[3];
    const float* gamma = (const float*)d_in[4];
    const float* beta  = (const float*)d_in[5];
    const float* w_in  = (const float*)d_in[6];
    const float* b_in  = (const float*)d_in[7];
    const float* w_out = (const float*)d_in[8];
    const float* b_out = (const float*)d_in[9];
    const int*   lenp  = (const int*)d_in[10];
    float* out = (float*)d_out;

    float *xn;
    __nv_bfloat16 *xh, *xl, *qh, *ql, *ch, *cl, *wih, *wil, *woh, *wol;
    cudaGetSymbolAddress((void**)&xn,  g_xn);
    cudaGetSymbolAddress((void**)&xh,  g_xn_h);
    cudaGetSymbolAddress((void**)&xl,  g_xn_l);
    cudaGetSymbolAddress((void**)&qh,  g_qkv_h);
    cudaGetSymbolAddress((void**)&ql,  g_qkv_l);
    cudaGetSymbolAddress((void**)&ch,  g_cmb_h);
    cudaGetSymbolAddress((void**)&cl,  g_cmb_l);
    cudaGetSymbolAddress((void**)&wih, g_winT_h);
    cudaGetSymbolAddress((void**)&wil, g_winT_l);
    cudaGetSymbolAddress((void**)&woh, g_woutT_h);
    cudaGetSymbolAddress((void**)&wol, g_woutT_l);

    cudaFuncSetAttribute(gemm_kernel<1>, cudaFuncAttributeMaxDynamicSharedMemorySize, GEMM_SMEM);
    cudaFuncSetAttribute(gemm_kernel<0>, cudaFuncAttributeMaxDynamicSharedMemorySize, GEMM_SMEM);
    cudaFuncSetAttribute(attn_kernel,    cudaFuncAttributeMaxDynamicSharedMemorySize, ATTN_SMEM);

    ln_kernel<<<N_TOK, 256>>>(x, gamma, beta, xn, xh, xl);
    wtr_kernel<<<dim3(MIDW / 32, HID / 32), 256>>>(w_in, wih, wil, HID, MIDW);
    wtr_kernel<<<dim3(HID / 32, COMBW / 32), 256>>>(w_out, woh, wol, COMBW, HID);

    gemm_kernel<1><<<dim3(MIDW / 128, N_TOK / 128), 256, GEMM_SMEM>>>(
        xh, xl, wih, wil, HID, b_in, psin, pcos, qh, ql, ch, cl, nullptr, nullptr);

    attn_kernel<<<dim3(N_TOK / 256, NH), 256, ATTN_SMEM>>>(lenp, qh, ql, ch, cl);

    gemm_kernel<0><<<dim3(HID / 128, N_TOK / 128), 256, GEMM_SMEM>>>(
        ch, cl, woh, wol, COMBW, b_out, nullptr, nullptr, nullptr, nullptr, nullptr, nullptr, xn, out);
}